// round 12
// baseline (speedup 1.0000x reference)
#include <cuda_runtime.h>
#include <cuda_fp16.h>

#define HH 1024
#define WW 1024
#define NPIX (HH * WW)

// Persistent device-global scratch (no cudaMalloc allowed).
__device__ uint2  g_Ph[NPIX];   // 4 fp16 weights (up,dn,lf,rt) per pixel; zeros at seeds
__device__ float2 g_buf[NPIX];  // ping-pong partner of d_out

__global__ __launch_bounds__(256)
void rw_setup_kernel(const float* __restrict__ img,
                     const int* __restrict__ seeds,
                     float2* __restrict__ x0)
{
    int j = blockIdx.x * 32 + threadIdx.x;
    int i = blockIdx.y * blockDim.y + threadIdx.y;
    int idx = i * WW + j;

    float c  = img[idx];
    bool  cb = (c > 0.1f);

    const int di[4] = {-1, 1, 0, 0};
    const int dj[4] = { 0, 0,-1, 1};

    float w[4];
    float rowsum = 0.0f;
#pragma unroll
    for (int d = 0; d < 4; d++) {
        int ni = i + di[d], nj = j + dj[d];
        bool valid = (ni >= 0) && (ni < HH) && (nj >= 0) && (nj < WW);
        int nidx = (valid ? ni : i) * WW + (valid ? nj : j);
        float nb = img[nidx];
        float same = ((nb > 0.1f) != cb) ? 1.0f : 0.0f;
        float diff = c - nb + same;
        float wt = valid ? expf(-1.0f - fabsf(diff)) : 0.0f;
        w[d] = wt;
        rowsum += wt;
    }
    float inv = 1.0f / rowsum;

    int s = seeds[idx];
    uint2 ph = make_uint2(0u, 0u);
    if (!s) {
        __half2 h01 = __floats2half2_rn(w[0] * inv, w[1] * inv);
        __half2 h23 = __floats2half2_rn(w[2] * inv, w[3] * inv);
        ph.x = *reinterpret_cast<unsigned*>(&h01);
        ph.y = *reinterpret_cast<unsigned*>(&h23);
    }
    g_Ph[idx] = ph;

    float2 x;
    x.x = (s == 1) ? 1.0f : 0.0f;
    x.y = (s == 2) ? 1.0f : 0.0f;
    x0[idx] = x;
}

// ---------------------------------------------------------------------------
// Four Jacobi steps per launch. Tile 58x26. Lane = column, thread = vertical
// pair of pixels: per pair only the 4-row center column comes from memory
// (4 LDS/LDG); lf/rt neighbors via warp shuffle (no L1 bank traffic).
// Phase widths 64/62/60/58 -> two 32-lane column groups, >=91% lane util.
//   sA: 64x32 buffer, logical origin (-3,-3)   sB: 62x30, origin (-2,-2)
//   p0: global->sA (R=3)  p1: sA->sB (R=2)  p2: sB->sA (R=1)  p3: sA->global
// ---------------------------------------------------------------------------
#define TX 58
#define TY 26
#define SAW 64
#define SBW 62

__device__ __forceinline__ float2 shup(float2 v) {
    float2 r;
    r.x = __shfl_up_sync(0xffffffffu, v.x, 1);
    r.y = __shfl_up_sync(0xffffffffu, v.y, 1);
    return r;
}
__device__ __forceinline__ float2 shdn(float2 v) {
    float2 r;
    r.x = __shfl_down_sync(0xffffffffu, v.x, 1);
    r.y = __shfl_down_sync(0xffffffffu, v.y, 1);
    return r;
}

// One Jacobi sub-step over a (58+2R) x (26+2R) region.
//  R: region radius. SI/SO: input/output strides. GIN: input is global.
//  GOUT: output is global. GUARD: coordinates may leave the image.
// in_log/out_log point at logical pixel (by, bx) of their buffers.
template<int R, int SI, int SO, bool GIN, bool GOUT, bool GUARD>
__device__ __forceinline__
void sphase(int lane, int wid, int by, int bx,
            const float2* __restrict__ in_log,
            float2* __restrict__ out_log)
{
    constexpr int H  = 26 + 2 * R;   // region rows (even)
    constexpr int NT = H;            // (H/2 pair-rows) x 2 col-groups

    for (int t = wid; t < NT; t += 8) {
        int pr = t >> 1;
        int g  = t & 1;
        int ro = 2 * pr - R;              // logical row of first output px
        int co = -R + g * 32 + lane;      // logical col (lane-contiguous)
        bool act = (co <= 57 + R);        // inside region width

        // ---- P loads (fp16, L2-resident) ----
        uint2 ph1, ph2;
        if (GUARD) {
            bool vc = (unsigned)(bx + co) < WW;
            ph1 = (vc && (unsigned)(by + ro)     < HH) ? g_Ph[(by + ro)     * WW + (bx + co)] : make_uint2(0u, 0u);
            ph2 = (vc && (unsigned)(by + ro + 1) < HH) ? g_Ph[(by + ro + 1) * WW + (bx + co)] : make_uint2(0u, 0u);
        } else {
            const uint2* pp = g_Ph + (by + ro) * WW + (bx + co);
            ph1 = pp[0];
            ph2 = pp[WW];
        }

        // ---- 4-row center column ----
        const float2* ip = in_log + ro * SI + co;
        float2 a, b, c, d;
        if (GIN && GUARD) {
            const float2 z = make_float2(0.f, 0.f);
            bool vc  = (unsigned)(bx + co) < WW;
            a = (vc && (unsigned)(by + ro - 1) < HH) ? ip[-SI]    : z;
            b = (vc && (unsigned)(by + ro)     < HH) ? ip[0]      : z;
            c = (vc && (unsigned)(by + ro + 1) < HH) ? ip[SI]     : z;
            d = (vc && (unsigned)(by + ro + 2) < HH) ? ip[2 * SI] : z;
        } else {
            a = ip[-SI];
            b = ip[0];
            c = ip[SI];
            d = ip[2 * SI];
        }

        // ---- horizontal neighbors via shuffle; group edges from memory ----
        float2 lf0 = shup(b), lf1 = shup(c);
        float2 rt0 = shdn(b), rt1 = shdn(c);
        if (lane == 0) {
            if (GIN && GUARD) {
                const float2 z = make_float2(0.f, 0.f);
                bool vcl = (unsigned)(bx + co - 1) < WW;
                lf0 = (vcl && (unsigned)(by + ro)     < HH) ? ip[-1]     : z;
                lf1 = (vcl && (unsigned)(by + ro + 1) < HH) ? ip[SI - 1] : z;
            } else {
                lf0 = ip[-1];
                lf1 = ip[SI - 1];
            }
        }
        if (lane == 31) {
            if (GIN && GUARD) {
                const float2 z = make_float2(0.f, 0.f);
                bool vcr = (unsigned)(bx + co + 1) < WW;
                rt0 = (vcr && (unsigned)(by + ro)     < HH) ? ip[1]      : z;
                rt1 = (vcr && (unsigned)(by + ro + 1) < HH) ? ip[SI + 1] : z;
            } else {
                rt0 = ip[1];
                rt1 = ip[SI + 1];
            }
        }

        // ---- stencil (fp32; self = 1 - sum keeps rows exactly stochastic) ----
        float2 p1a = __half22float2(*reinterpret_cast<__half2*>(&ph1.x));  // (up,dn)
        float2 p1b = __half22float2(*reinterpret_cast<__half2*>(&ph1.y));  // (lf,rt)
        float2 p2a = __half22float2(*reinterpret_cast<__half2*>(&ph2.x));
        float2 p2b = __half22float2(*reinterpret_cast<__half2*>(&ph2.y));

        float s1 = 1.0f - ((p1a.x + p1a.y) + (p1b.x + p1b.y));
        float s2 = 1.0f - ((p2a.x + p2a.y) + (p2b.x + p2b.y));
        float2 o0, o1;
        o0.x = p1a.x*a.x + p1a.y*c.x + p1b.x*lf0.x + p1b.y*rt0.x + s1*b.x;
        o0.y = p1a.x*a.y + p1a.y*c.y + p1b.x*lf0.y + p1b.y*rt0.y + s1*b.y;
        o1.x = p2a.x*b.x + p2a.y*d.x + p2b.x*lf1.x + p2b.y*rt1.x + s2*c.x;
        o1.y = p2a.x*b.y + p2a.y*d.y + p2b.x*lf1.y + p2b.y*rt1.y + s2*c.y;

        // ---- store (inactive lanes never store) ----
        if (GOUT && GUARD) {
            if (act && (unsigned)(bx + co) < WW) {
                if ((unsigned)(by + ro)     < HH) out_log[ro * SO + co]       = o0;
                if ((unsigned)(by + ro + 1) < HH) out_log[(ro + 1) * SO + co] = o1;
            }
        } else if (act) {
            out_log[ro * SO + co]       = o0;
            out_log[(ro + 1) * SO + co] = o1;
        }
    }
}

template<bool GUARD>
__device__ __forceinline__
void rw_body(int lane, int wid, int by, int bx,
             const float2* __restrict__ xin, float2* __restrict__ xout,
             float2* __restrict__ sAl, float2* __restrict__ sBl)
{
    const float2* gin  = xin  + by * WW + bx;
    float2*       gout = xout + by * WW + bx;

    sphase<3, WW,  SAW, true,  false, GUARD>(lane, wid, by, bx, gin, sAl);
    __syncthreads();
    sphase<2, SAW, SBW, false, false, GUARD>(lane, wid, by, bx, sAl, sBl);
    __syncthreads();
    sphase<1, SBW, SAW, false, false, GUARD>(lane, wid, by, bx, sBl, sAl);
    __syncthreads();
    sphase<0, SAW, WW,  false, true,  GUARD>(lane, wid, by, bx, sAl, gout);
}

__global__ __launch_bounds__(256, 7)
void rw_step4_kernel(const float2* __restrict__ xin,
                     float2* __restrict__ xout)
{
    __shared__ float2 sA[SAW * 32 + 16];  // 64x32 + stray-read pad
    __shared__ float2 sB[SBW * 30 + 16];  // 62x30 + pad

    const int tid  = threadIdx.x;
    const int lane = tid & 31;
    const int wid  = tid >> 5;
    const int bx   = blockIdx.x * TX;
    const int by   = blockIdx.y * TY;

    float2* sAl = sA + 3 * SAW + 3;  // logical (by, bx)
    float2* sBl = sB + 2 * SBW + 2;

    // interior: all global reads (incl. radius-4 lf/rt edges) stay in-image
    const bool interior = (bx >= 4) && (bx + 61 <= WW - 1) &&
                          (by >= 4) && (by + 29 <= HH - 1) &&
                          (bx + TX <= WW) && (by + TY <= HH);
    if (interior) rw_body<false>(lane, wid, by, bx, xin, xout, sAl, sBl);
    else          rw_body<true >(lane, wid, by, bx, xin, xout, sAl, sBl);
}

extern "C" void kernel_launch(void* const* d_in, const int* in_sizes, int n_in,
                              void* d_out, int out_size)
{
    const float* img   = (const float*)d_in[0];
    const int*   seeds = (const int*)d_in[1];
    float2*      A     = (float2*)d_out;

    float2* B = nullptr;
    cudaGetSymbolAddress((void**)&B, g_buf);

    {
        dim3 blk(32, 8);
        dim3 grd(WW / 32, HH / 8);
        // x0 written into B; 25 quad-step kernels alternate B->A->B...,
        // t=24 (even) writes A = d_out.
        rw_setup_kernel<<<grd, blk>>>(img, seeds, B);
    }

    dim3 blk(256);
    dim3 grd((WW + TX - 1) / TX, (HH + TY - 1) / TY);  // 18 x 40 = 720 blocks
    for (int t = 0; t < 25; t++) {
        const float2* xin  = (t & 1) ? A : B;
        float2*       xout = (t & 1) ? B : A;
        rw_step4_kernel<<<grd, blk>>>(xin, xout);
    }
}

// round 13
// speedup vs baseline: 1.1480x; 1.1480x over previous
#include <cuda_runtime.h>
#include <cuda_fp16.h>

#define HH 1024
#define WW 1024
#define NPIX (HH * WW)

// Persistent device-global scratch (no cudaMalloc allowed).
__device__ uint2  g_Ph[NPIX];   // 4 fp16 weights (up,dn,lf,rt) per pixel; zeros at seeds
__device__ float2 g_buf[NPIX];  // ping-pong partner of d_out

__global__ __launch_bounds__(256)
void rw_setup_kernel(const float* __restrict__ img,
                     const int* __restrict__ seeds,
                     float2* __restrict__ x0)
{
    int j = blockIdx.x * 32 + threadIdx.x;
    int i = blockIdx.y * blockDim.y + threadIdx.y;
    int idx = i * WW + j;

    float c  = img[idx];
    bool  cb = (c > 0.1f);

    const int di[4] = {-1, 1, 0, 0};
    const int dj[4] = { 0, 0,-1, 1};

    float w[4];
    float rowsum = 0.0f;
#pragma unroll
    for (int d = 0; d < 4; d++) {
        int ni = i + di[d], nj = j + dj[d];
        bool valid = (ni >= 0) && (ni < HH) && (nj >= 0) && (nj < WW);
        int nidx = (valid ? ni : i) * WW + (valid ? nj : j);
        float nb = img[nidx];
        float same = ((nb > 0.1f) != cb) ? 1.0f : 0.0f;
        float diff = c - nb + same;
        float wt = valid ? expf(-1.0f - fabsf(diff)) : 0.0f;
        w[d] = wt;
        rowsum += wt;
    }
    float inv = 1.0f / rowsum;

    int s = seeds[idx];
    uint2 ph = make_uint2(0u, 0u);
    if (!s) {
        __half2 h01 = __floats2half2_rn(w[0] * inv, w[1] * inv);
        __half2 h23 = __floats2half2_rn(w[2] * inv, w[3] * inv);
        ph.x = *reinterpret_cast<unsigned*>(&h01);
        ph.y = *reinterpret_cast<unsigned*>(&h23);
    }
    g_Ph[idx] = ph;

    float2 x;
    x.x = (s == 1) ? 1.0f : 0.0f;
    x.y = (s == 2) ? 1.0f : 0.0f;
    x0[idx] = x;
}

// ---------------------------------------------------------------------------
// Four Jacobi steps per launch, tile 64x32, 512 threads, 4 blocks/SM
// (single wave: 512 blocks <= 148*4). Vertical-pair threads (2 px/thread,
// shared 4-row center column -> 8 LDS per 2 px). Phase 0 reads x straight
// from global. P in fp16 (uint2) from L2, fp32 math, self = 1 - sum(p)
// keeps rows exactly stochastic.
//   sA: 38x70 logical origin (by-3, bx-3)   sB: 36x68 origin (by-2, bx-2)
//   p0: global->sA (R=3)  p1: sA->sB (R=2)  p2: sB->sA (R=1)  p3: sA->global
// ---------------------------------------------------------------------------
#define TX 64
#define TY 32
#define NTHR 512
#define SAW 70
#define SBW 68

__device__ __forceinline__
void unpack_p(uint2 ph, float2& w01, float2& w23)
{
    w01 = __half22float2(*reinterpret_cast<__half2*>(&ph.x));
    w23 = __half22float2(*reinterpret_cast<__half2*>(&ph.y));
}

// One Jacobi sub-step over a DH x DW output region, 2 vertically-adjacent px
// per thread. in_log/out_log point at logical pixel (by, bx) of their buffers.
//  DH/DW: region rows (even) / cols   R: region radius (rows/cols in [-R, ..))
//  SI/SO: input/output strides   GUARD: coords may leave the image
//  GIN: input is global memory (x reads guarded when GUARD)
template<int DH, int DW, int R, int SI, int SO, bool GUARD, bool GIN>
__device__ __forceinline__
void pair_phase(int tid, int by, int bx,
                const float2* __restrict__ in_log,
                float2* __restrict__ out_log)
{
    constexpr int TOT   = (DH / 2) * DW;
    constexpr int NITER = (TOT + NTHR - 1) / NTHR;
    constexpr bool EXACT = (NITER * NTHR == TOT);

    for (int it = 0; it < NITER; it++) {
        int e = tid + it * NTHR;
        if (EXACT || e < TOT) {
            int pr = e / DW;
            int cc = e - pr * DW;
            int ro = 2 * pr - R;   // logical row of first output px
            int co = cc - R;       // logical col

            // --- P loads first (deep MLP; L2-resident, fp16) ---
            const uint2* pp = g_Ph + (by + ro) * WW + (bx + co);
            uint2 ph1, ph2;
            if (GUARD) {
                bool vc = (unsigned)(bx + co) < WW;
                ph1 = (vc && (unsigned)(by + ro)     < HH) ? pp[0]  : make_uint2(0u, 0u);
                ph2 = (vc && (unsigned)(by + ro + 1) < HH) ? pp[WW] : make_uint2(0u, 0u);
            } else {
                ph1 = pp[0];
                ph2 = pp[WW];
            }

            // --- x reads: 4-row center column + lf/rt for both rows ---
            const float2* ip = in_log + ro * SI + co;
            float2 a, b, c, d, lf0, rt0, lf1, rt1;
            if (GIN && GUARD) {
                bool vc  = (unsigned)(bx + co)     < WW;
                bool vcl = (unsigned)(bx + co - 1) < WW;
                bool vcr = (unsigned)(bx + co + 1) < WW;
                bool vym = (unsigned)(by + ro - 1) < HH;
                bool vy0 = (unsigned)(by + ro)     < HH;
                bool vy1 = (unsigned)(by + ro + 1) < HH;
                bool vy2 = (unsigned)(by + ro + 2) < HH;
                const float2 z = make_float2(0.f, 0.f);
                a   = (vym && vc ) ? ip[-SI]     : z;
                b   = (vy0 && vc ) ? ip[0]       : z;
                c   = (vy1 && vc ) ? ip[SI]      : z;
                d   = (vy2 && vc ) ? ip[2 * SI]  : z;
                lf0 = (vy0 && vcl) ? ip[-1]      : z;
                rt0 = (vy0 && vcr) ? ip[1]       : z;
                lf1 = (vy1 && vcl) ? ip[SI - 1]  : z;
                rt1 = (vy1 && vcr) ? ip[SI + 1]  : z;
            } else {
                a   = ip[-SI];
                b   = ip[0];
                c   = ip[SI];
                d   = ip[2 * SI];
                lf0 = ip[-1];
                rt0 = ip[1];
                lf1 = ip[SI - 1];
                rt1 = ip[SI + 1];
            }

            float2 p1a, p1b, p2a, p2b;
            unpack_p(ph1, p1a, p1b);   // p1a=(up,dn) p1b=(lf,rt)
            unpack_p(ph2, p2a, p2b);

            float s1 = 1.0f - ((p1a.x + p1a.y) + (p1b.x + p1b.y));
            float s2 = 1.0f - ((p2a.x + p2a.y) + (p2b.x + p2b.y));
            float2 o0, o1;
            o0.x = p1a.x*a.x + p1a.y*c.x + p1b.x*lf0.x + p1b.y*rt0.x + s1*b.x;
            o0.y = p1a.x*a.y + p1a.y*c.y + p1b.x*lf0.y + p1b.y*rt0.y + s1*b.y;
            o1.x = p2a.x*b.x + p2a.y*d.x + p2b.x*lf1.x + p2b.y*rt1.x + s2*c.x;
            o1.y = p2a.x*b.y + p2a.y*d.y + p2b.x*lf1.y + p2b.y*rt1.y + s2*c.y;

            out_log[ro * SO + co]       = o0;
            out_log[(ro + 1) * SO + co] = o1;
        }
    }
}

template<bool GUARD>
__device__ __forceinline__
void rw_body(int tid, int by, int bx,
             const float2* __restrict__ xin, float2* __restrict__ xout,
             float2* __restrict__ sAl, float2* __restrict__ sBl)
{
    const float2* gin  = xin  + by * WW + bx;
    float2*       gout = xout + by * WW + bx;

    pair_phase<38, 70, 3, WW,  SAW, GUARD, true >(tid, by, bx, gin, sAl);  // global->sA
    __syncthreads();
    pair_phase<36, 68, 2, SAW, SBW, GUARD, false>(tid, by, bx, sAl, sBl);  // sA->sB
    __syncthreads();
    pair_phase<34, 66, 1, SBW, SAW, GUARD, false>(tid, by, bx, sBl, sAl);  // sB->sA
    __syncthreads();
    // final tile is fully in-image -> never guarded
    pair_phase<32, 64, 0, SAW, WW,  false, false>(tid, by, bx, sAl, gout); // sA->global
}

__global__ __launch_bounds__(NTHR, 4)
void rw_step4_kernel(const float2* __restrict__ xin,
                     float2* __restrict__ xout)
{
    __shared__ float2 sA[38 * SAW];  // 21.3 KB
    __shared__ float2 sB[36 * SBW];  // 19.1 KB

    const int tid = threadIdx.x;
    const int bx  = blockIdx.x * TX;
    const int by  = blockIdx.y * TY;

    float2* sAl = sA + 3 * SAW + 3;  // logical (by, bx)
    float2* sBl = sB + 2 * SBW + 2;

    // p0 touches x rows by-4..by+35, cols bx-4..bx+67
    const bool interior = (bx >= 4) && (bx + 68 <= WW) &&
                          (by >= 4) && (by + 36 <= HH);
    if (interior) rw_body<false>(tid, by, bx, xin, xout, sAl, sBl);
    else          rw_body<true >(tid, by, bx, xin, xout, sAl, sBl);
}

extern "C" void kernel_launch(void* const* d_in, const int* in_sizes, int n_in,
                              void* d_out, int out_size)
{
    const float* img   = (const float*)d_in[0];
    const int*   seeds = (const int*)d_in[1];
    float2*      A     = (float2*)d_out;

    float2* B = nullptr;
    cudaGetSymbolAddress((void**)&B, g_buf);

    {
        dim3 blk(32, 8);
        dim3 grd(WW / 32, HH / 8);
        // x0 written into B; 25 quad-step kernels alternate B->A->B...,
        // t=24 (even) writes A = d_out.
        rw_setup_kernel<<<grd, blk>>>(img, seeds, B);
    }

    dim3 blk(NTHR);
    dim3 grd(WW / TX, HH / TY);   // 16 x 32 = 512 blocks
    for (int t = 0; t < 25; t++) {
        const float2* xin  = (t & 1) ? A : B;
        float2*       xout = (t & 1) ? B : A;
        rw_step4_kernel<<<grd, blk>>>(xin, xout);
    }
}